// round 8
// baseline (speedup 1.0000x reference)
#include <cuda_runtime.h>
#include <cstdint>

// Problem constants (match reference setup_inputs)
#define NN 100000
#define EE 1600000
#define DD 64

// Scratch aggregation buffer. float4 for guaranteed 16B alignment.
__device__ float4 g_agg4[(size_t)NN * (DD / 4)];

// 1 if edge_index buffer is int64, 0 if int32 (JAX x64-disabled downgrades).
__device__ int g_idx_is64;

// ---------------------------------------------------------------------------
// Phase B: zero the aggregation buffer. Thread 0 of block 0 also detects the
// edge_index width (indices < 2^17, so int64 => odd 32-bit words all zero).
// ---------------------------------------------------------------------------
__global__ void __launch_bounds__(256) zero_agg_kernel(
    const unsigned int* __restrict__ ei_words)
{
    int i = blockIdx.x * blockDim.x + threadIdx.x;
    if (i == 0) {
        int zeros = 0;
        #pragma unroll
        for (int s = 0; s < 64; s++) zeros += (ei_words[2 * s + 1] == 0u) ? 1 : 0;
        g_idx_is64 = (zeros >= 60) ? 1 : 0;
    }
    const int total4 = NN * (DD / 4);
    if (i < total4) g_agg4[i] = make_float4(0.f, 0.f, 0.f, 0.f);
}

// ---------------------------------------------------------------------------
// Phase A: edge scatter. 16 threads/edge, red.global.add.v4 into g_agg.
// ---------------------------------------------------------------------------
__global__ void __launch_bounds__(256) scatter_kernel(
    const float* __restrict__ x,
    const void* __restrict__ edge_index, // [2, E], int32 or int64
    const float* __restrict__ edge_attr)
{
    int gid = blockIdx.x * blockDim.x + threadIdx.x;
    int e = gid >> 4;
    int q = gid & 15;
    if (e >= EE) return;

    int src, dst;
    if (g_idx_is64) {
        const long long* ei = (const long long*)edge_index;
        src = (int)ei[e];
        dst = (int)ei[EE + e];
    } else {
        const int* ei = (const int*)edge_index;
        src = ei[e];
        dst = ei[EE + e];
    }
    float w = edge_attr[e];

    float4 v = reinterpret_cast<const float4*>(x)[(size_t)src * 16 + q];
    v.x *= w; v.y *= w; v.z *= w; v.w *= w;

    float* p = (float*)(g_agg4 + (size_t)dst * 16 + q);
    asm volatile("red.global.add.v4.f32 [%0], {%1, %2, %3, %4};"
                 :: "l"(p), "f"(v.x), "f"(v.y), "f"(v.z), "f"(v.w)
                 : "memory");
}

// ---------------------------------------------------------------------------
// Packed f32x2 helpers (sm_103a).
// ---------------------------------------------------------------------------
typedef unsigned long long u64;

__device__ __forceinline__ u64 pack2(float lo, float hi) {
    u64 r;
    asm("mov.b64 %0, {%1, %2};" : "=l"(r)
        : "r"(__float_as_uint(lo)), "r"(__float_as_uint(hi)));
    return r;
}
__device__ __forceinline__ void unpack2(u64 v, float& lo, float& hi) {
    unsigned int a, b;
    asm("mov.b64 {%0, %1}, %2;" : "=r"(a), "=r"(b) : "l"(v));
    lo = __uint_as_float(a);
    hi = __uint_as_float(b);
}
__device__ __forceinline__ void ffma2(u64& acc, u64 a, u64 b) {
    asm("fma.rn.f32x2 %0, %1, %2, %0;" : "+l"(acc) : "l"(a), "l"(b));
}

// ---------------------------------------------------------------------------
// Phase C: out = relu(agg @ W_rel^T + b_rel + x @ W_root^T)
//
// 256 threads/block, 64 nodes/block. t = tid>>4 -> rows t*4..t*4+3,
// j = tid&15 -> outputs 4j..4j+3 held as 2 f32x2 accumulators per row
// (adjacent OUTPUTS paired). Weight pairs come straight out of the [k][o]
// transposed shared layout as u64s (one LDS.128 = both output pairs).
// Row operands are stored DUPLICATED in shared ((v,v) u64), so the broadcast
// multiplier is a direct LDS. Inner loop has ZERO pack MOVs:
// per kc-chunk of 4: 8 weight LDS.128 + 16 row LDS.128 + 64 FFMA2.
// ---------------------------------------------------------------------------
#define RPB 64     // rows (nodes) per block
#define RP2 66     // u64 row stride for duplicated rows (66*8=528, 16B mult)

__global__ void __launch_bounds__(256, 2) output_kernel(
    const float* __restrict__ x,
    const float* __restrict__ W_rel,   // [64,64] row-major W[o][k]
    const float* __restrict__ b_rel,   // [64]
    const float* __restrict__ W_root,  // [64,64]
    float* __restrict__ out)
{
    __shared__ __align__(16) float Wr[DD * DD];   // Wr[k*64 + o]
    __shared__ __align__(16) float Wo[DD * DD];
    __shared__ __align__(16) u64 sad[RPB * RP2];  // agg rows, duplicated
    __shared__ __align__(16) u64 sxd[RPB * RP2];  // x rows, duplicated

    int tid = threadIdx.x;
    int nb = blockIdx.x * RPB;

    // Transpose-load both weight matrices into shared.
    #pragma unroll
    for (int i = tid; i < DD * DD; i += 256) {
        int o = i >> 6;
        int k = i & 63;
        Wr[k * DD + o] = W_rel[i];
        Wo[k * DD + o] = W_root[i];
    }

    // Stage RPB agg rows + RPB x rows as duplicated u64s (zero OOB rows).
    #pragma unroll
    for (int it = 0; it < RPB / 16; it++) {
        int i = tid + it * 256;        // 0..1023 float4 slots
        int row = i >> 4;
        int q = i & 15;
        float4 a4 = make_float4(0.f, 0.f, 0.f, 0.f);
        float4 r4 = make_float4(0.f, 0.f, 0.f, 0.f);
        if (nb + row < NN) {
            a4 = g_agg4[(size_t)(nb + row) * 16 + q];
            r4 = reinterpret_cast<const float4*>(x)[(size_t)(nb + row) * 16 + q];
        }
        u64* ad = sad + row * RP2 + q * 4;
        u64* xd = sxd + row * RP2 + q * 4;
        ad[0] = pack2(a4.x, a4.x); ad[1] = pack2(a4.y, a4.y);
        ad[2] = pack2(a4.z, a4.z); ad[3] = pack2(a4.w, a4.w);
        xd[0] = pack2(r4.x, r4.x); xd[1] = pack2(r4.y, r4.y);
        xd[2] = pack2(r4.z, r4.z); xd[3] = pack2(r4.w, r4.w);
    }
    __syncthreads();

    int t = tid >> 4;                  // row group -> rows t*4..t*4+3
    int j = tid & 15;                  // outputs 4j..4j+3
    int rb = t * 4;

    // acc[r][0] = (out 4j, 4j+1), acc[r][1] = (out 4j+2, 4j+3)
    float4 bias = reinterpret_cast<const float4*>(b_rel)[j];
    u64 acc[4][2];
    {
        u64 b01 = pack2(bias.x, bias.y);
        u64 b23 = pack2(bias.z, bias.w);
        #pragma unroll
        for (int r = 0; r < 4; r++) { acc[r][0] = b01; acc[r][1] = b23; }
    }

    const u64* abase = sad + rb * RP2;
    const u64* xbase = sxd + rb * RP2;

    #pragma unroll 1
    for (int kc = 0; kc < DD; kc += 4) {
        // Weight pairs for 4 k-steps: one LDS.128 each = 2 u64 output pairs.
        ulonglong2 wrp[4], wop[4];
        #pragma unroll
        for (int kk = 0; kk < 4; kk++) {
            wrp[kk] = *reinterpret_cast<const ulonglong2*>(Wr + (kc + kk) * DD + 4 * j);
            wop[kk] = *reinterpret_cast<const ulonglong2*>(Wo + (kc + kk) * DD + 4 * j);
        }

        #pragma unroll
        for (int r = 0; r < 4; r++) {
            // Duplicated row operands: 2 LDS.128 per array per row = 4 kk.
            ulonglong2 a01 = *reinterpret_cast<const ulonglong2*>(abase + r * RP2 + kc);
            ulonglong2 a23 = *reinterpret_cast<const ulonglong2*>(abase + r * RP2 + kc + 2);
            ulonglong2 x01 = *reinterpret_cast<const ulonglong2*>(xbase + r * RP2 + kc);
            ulonglong2 x23 = *reinterpret_cast<const ulonglong2*>(xbase + r * RP2 + kc + 2);

            ffma2(acc[r][0], a01.x, wrp[0].x); ffma2(acc[r][1], a01.x, wrp[0].y);
            ffma2(acc[r][0], x01.x, wop[0].x); ffma2(acc[r][1], x01.x, wop[0].y);

            ffma2(acc[r][0], a01.y, wrp[1].x); ffma2(acc[r][1], a01.y, wrp[1].y);
            ffma2(acc[r][0], x01.y, wop[1].x); ffma2(acc[r][1], x01.y, wop[1].y);

            ffma2(acc[r][0], a23.x, wrp[2].x); ffma2(acc[r][1], a23.x, wrp[2].y);
            ffma2(acc[r][0], x23.x, wop[2].x); ffma2(acc[r][1], x23.x, wop[2].y);

            ffma2(acc[r][0], a23.y, wrp[3].x); ffma2(acc[r][1], a23.y, wrp[3].y);
            ffma2(acc[r][0], x23.y, wop[3].x); ffma2(acc[r][1], x23.y, wop[3].y);
        }
    }

    // Epilogue: unpack output pairs, relu, one float4 store per row.
    #pragma unroll
    for (int r = 0; r < 4; r++) {
        int nr = nb + rb + r;
        if (nr < NN) {
            float4 v;
            unpack2(acc[r][0], v.x, v.y);
            unpack2(acc[r][1], v.z, v.w);
            v.x = fmaxf(v.x, 0.f); v.y = fmaxf(v.y, 0.f);
            v.z = fmaxf(v.z, 0.f); v.w = fmaxf(v.w, 0.f);
            reinterpret_cast<float4*>(out)[(size_t)nr * 16 + j] = v;
        }
    }
}

// ---------------------------------------------------------------------------
// Launch: zero+detect -> scatter -> output (capture stream, no syncs)
// Input order: x, edge_index, edge_attr, W_rel, b_rel, W_root
// ---------------------------------------------------------------------------
extern "C" void kernel_launch(void* const* d_in, const int* in_sizes, int n_in,
                              void* d_out, int out_size)
{
    const float* x     = (const float*)d_in[0];
    const void*  ei    = d_in[1];
    const float* ea    = (const float*)d_in[2];
    const float* Wrel  = (const float*)d_in[3];
    const float* brel  = (const float*)d_in[4];
    const float* Wroot = (const float*)d_in[5];
    float*       out   = (float*)d_out;

    zero_agg_kernel<<<(NN * (DD / 4) + 255) / 256, 256>>>(
        (const unsigned int*)ei);

    {
        long long total = (long long)EE * 16;
        int blocks = (int)((total + 255) / 256);
        scatter_kernel<<<blocks, 256>>>(x, ei, ea);
    }

    output_kernel<<<(NN + RPB - 1) / RPB, 256>>>(x, Wrel, brel, Wroot, out);
}